// round 16
// baseline (speedup 1.0000x reference)
#include <cuda_runtime.h>
#include <cuda_bf16.h>
#include <math.h>
#include <stdint.h>

#define S_LEN 2048
#define BATCH 4
#define HID 1024
#define NHEADS 16
#define HDIM 64
#define M_ROWS (S_LEN * BATCH)   // 8192
#define QKV_N (3 * HID)          // 3072
#define GK HID                   // K dim of both GEMMs = 1024
#define SCALE_L2E 0.18033688011112043f   // 0.125 * log2(e)  (pre-folded into Q)
#define MASK_L2  (-14426.950408889634f)  // -10000 * log2(e)

// ---------------- scratch (allocation-free: device globals) ----------------
__device__ int g_mask_is_i32;
__device__ uint32_t g_mask_bits[(size_t)BATCH * 16 * 32 * 256];   // 2 MB

#define QKV_ELEMS ((size_t)64 * S_LEN * HDIM)
__device__ __align__(16) __nv_bfloat16 g_Qh[QKV_ELEMS], g_Ql[QKV_ELEMS];
__device__ __align__(16) __nv_bfloat16 g_Kh[QKV_ELEMS], g_Kl[QKV_ELEMS];
__device__ __align__(16) __nv_bfloat16 g_Vh[QKV_ELEMS], g_Vl[QKV_ELEMS];

__device__ __align__(16) __nv_bfloat16 g_pA_hi[(size_t)M_ROWS * HID];
__device__ __align__(16) __nv_bfloat16 g_pA_lo[(size_t)M_ROWS * HID];
__device__ __align__(16) __nv_bfloat16 g_pWq_hi[(size_t)QKV_N * HID];
__device__ __align__(16) __nv_bfloat16 g_pWq_lo[(size_t)QKV_N * HID];
__device__ __align__(16) __nv_bfloat16 g_pWd_hi[(size_t)HID * HID];
__device__ __align__(16) __nv_bfloat16 g_pWd_lo[(size_t)HID * HID];

// ---------------- helpers ----------------
__device__ __forceinline__ uint32_t smem_to_u32(const void* p) {
    uint32_t a;
    asm("{ .reg .u64 t; cvta.to.shared.u64 t, %1; cvt.u32.u64 %0, t; }" : "=r"(a) : "l"(p));
    return a;
}
__device__ __forceinline__ void cp_async16(uint32_t dst, const void* src) {
    asm volatile("cp.async.cg.shared.global [%0], [%1], 16;" :: "r"(dst), "l"(src));
}
#define CP_COMMIT() asm volatile("cp.async.commit_group;" ::: "memory")
#define CP_WAIT0()  asm volatile("cp.async.wait_group 0;" ::: "memory")
#define CP_WAIT1()  asm volatile("cp.async.wait_group 1;" ::: "memory")

__device__ __forceinline__ void ldmx4(uint32_t* r, uint32_t addr) {
    asm volatile("ldmatrix.sync.aligned.m8n8.x4.shared.b16 {%0,%1,%2,%3}, [%4];"
                 : "=r"(r[0]), "=r"(r[1]), "=r"(r[2]), "=r"(r[3]) : "r"(addr));
}
__device__ __forceinline__ void ldmx4t(uint32_t* r, uint32_t addr) {
    asm volatile("ldmatrix.sync.aligned.m8n8.x4.trans.shared.b16 {%0,%1,%2,%3}, [%4];"
                 : "=r"(r[0]), "=r"(r[1]), "=r"(r[2]), "=r"(r[3]) : "r"(addr));
}
__device__ __forceinline__ void mma16816(float* c, const uint32_t* a, uint32_t b0, uint32_t b1) {
    asm volatile(
        "mma.sync.aligned.m16n8k16.row.col.f32.bf16.bf16.f32 "
        "{%0,%1,%2,%3}, {%4,%5,%6,%7}, {%8,%9}, {%0,%1,%2,%3};"
        : "+f"(c[0]), "+f"(c[1]), "+f"(c[2]), "+f"(c[3])
        : "r"(a[0]), "r"(a[1]), "r"(a[2]), "r"(a[3]), "r"(b0), "r"(b1));
}
__device__ __forceinline__ uint32_t packbf2(float vhigh, float vlow) {
    uint32_t r;
    asm("cvt.rn.bf16x2.f32 %0, %1, %2;" : "=r"(r) : "f"(vhigh), "f"(vlow));
    return r;
}
__device__ __forceinline__ void split_hilo(float v0, float v1, uint32_t& hi, uint32_t& lo) {
    hi = packbf2(v1, v0);
    const float h0 = __int_as_float(hi << 16);
    const float h1 = __int_as_float(hi & 0xFFFF0000u);
    lo = packbf2(v1 - h1, v0 - h0);
}
__device__ __forceinline__ float ex2(float x) {
    float y;
    asm("ex2.approx.f32 %0, %1;" : "=f"(y) : "f"(x));
    return y;
}

// ---------------------------------------------------------------------------
// Mask dtype detect
// ---------------------------------------------------------------------------
__global__ void detect_mask_dtype(const int* __restrict__ m) {
    int bad = 0;
#pragma unroll
    for (int i = 0; i < 32; i++) {
        unsigned v = (unsigned)m[threadIdx.x * 32 + i];
        bad |= (v > 1u);
    }
    unsigned any = __ballot_sync(0xFFFFFFFFu, bad);
    if (threadIdx.x == 0) g_mask_is_i32 = (any == 0) ? 1 : 0;
}

// ---------------------------------------------------------------------------
// Mask -> fragment-layout bitwords (verified in R11/R12)
// ---------------------------------------------------------------------------
__global__ void __launch_bounds__(256)
convert_mask_frag(const void* __restrict__ raw, uint32_t* __restrict__ out) {
    __shared__ unsigned char mt[128 * 64];
    const int blk = blockIdx.x;
    const int kt = blk & 31, qt = (blk >> 5) & 15, b = blk >> 9;
    const int tid = threadIdx.x;
    const size_t base = ((size_t)b * S_LEN + qt * 128) * S_LEN + kt * 64;

    if (g_mask_is_i32) {
        const int* m = (const int*)raw;
#pragma unroll
        for (int i = 0; i < 8; i++) {
            const int c = tid + i * 256;
            const int row = c >> 4, c4 = (c & 15) * 4;
            const int4 v = *(const int4*)(m + base + (size_t)row * S_LEN + c4);
            mt[row * 64 + c4 + 0] = (unsigned char)v.x;
            mt[row * 64 + c4 + 1] = (unsigned char)v.y;
            mt[row * 64 + c4 + 2] = (unsigned char)v.z;
            mt[row * 64 + c4 + 3] = (unsigned char)v.w;
        }
    } else {
        const unsigned char* m = (const unsigned char*)raw;
#pragma unroll
        for (int i = 0; i < 2; i++) {
            const int c = tid + i * 256;
            const int row = c >> 2, col = (c & 3) * 16;
            *(uint4*)&mt[row * 64 + col] =
                *(const uint4*)(m + base + (size_t)row * S_LEN + col);
        }
    }
    __syncthreads();

    const int g = tid >> 5, l = tid & 31;
    const int r0 = g * 16 + (l >> 2);
    const int c0 = 2 * (l & 3);
    uint32_t word = 0;
#pragma unroll
    for (int nt = 0; nt < 8; nt++) {
#pragma unroll
        for (int j = 0; j < 4; j++) {
            const int r = r0 + ((j >> 1) ? 8 : 0);
            const int c = c0 + nt * 8 + (j & 1);
            word |= (mt[r * 64 + c] ? 1u : 0u) << (nt * 4 + j);
        }
    }
    out[(size_t)blk * 256 + tid] = word;
}

// ---------------------------------------------------------------------------
// Pack fp32 -> hi/lo bf16 (row-major flat)
// ---------------------------------------------------------------------------
__global__ void __launch_bounds__(256)
pack_hilo(const float* __restrict__ src, __nv_bfloat16* __restrict__ hi,
          __nv_bfloat16* __restrict__ lo) {
    const size_t idx = (size_t)blockIdx.x * 256 + threadIdx.x;
    const float4 v = *(const float4*)(src + idx * 4);
    uint32_t h0, l0, h1, l1;
    split_hilo(v.x, v.y, h0, l0);
    split_hilo(v.z, v.w, h1, l1);
    *(uint2*)(hi + idx * 4) = make_uint2(h0, h1);
    *(uint2*)(lo + idx * 4) = make_uint2(l0, l1);
}

// ---------------------------------------------------------------------------
// bf16 hi/lo GEMM via mma.sync — 2 CTAs/SM, ONE sync per iter (unchanged).
// epi_mode 1 writes Q pre-scaled by SCALE_L2E.
// ---------------------------------------------------------------------------
#define GP 80
#define GT_TILE (128 * GP)
#define GT_STAGE (4 * GT_TILE)
#define GT_SMEM (2 * GT_STAGE)

__global__ void __launch_bounds__(256, 2)
gemm_mma(const __nv_bfloat16* __restrict__ Ahi, const __nv_bfloat16* __restrict__ Alo,
         const __nv_bfloat16* __restrict__ Bhi, const __nv_bfloat16* __restrict__ Blo,
         const float* __restrict__ bias, float* __restrict__ C, int n_dim, int epi_mode,
         __nv_bfloat16* qh, __nv_bfloat16* ql, __nv_bfloat16* kh,
         __nv_bfloat16* kl, __nv_bfloat16* vh, __nv_bfloat16* vl) {
    extern __shared__ __align__(1024) char smem[];
    const uint32_t sb = smem_to_u32(smem);
    const int tid = threadIdx.x;
    const int bx = blockIdx.x, by = blockIdx.y;
    const int w = tid >> 5, l = tid & 31;
    const int wm = w >> 1, wn = w & 1;

    const int c0row = tid >> 2,        c0col = tid & 3;
    const int c1row = (tid + 256) >> 2, c1col = (tid + 256) & 3;

    const __nv_bfloat16* srcs[4] = {Ahi, Alo, Bhi, Blo};
    const size_t rowbase[4] = {(size_t)by * 128, (size_t)by * 128,
                               (size_t)bx * 128, (size_t)bx * 128};

    float acc[2][8][4];
#pragma unroll
    for (int i = 0; i < 2; i++)
#pragma unroll
        for (int j = 0; j < 8; j++)
#pragma unroll
            for (int q = 0; q < 4; q++) acc[i][j][q] = 0.0f;

    const uint32_t a_lane = (uint32_t)(l & 15) * GP + ((l >> 4) & 1) * 16;
    const uint32_t b_lane = (uint32_t)((l & 7) + ((l >> 4) & 1) * 8) * GP + ((l >> 3) & 1) * 16;

    auto issue = [&](int s, int k0) {
        const uint32_t st = sb + s * GT_STAGE;
#pragma unroll
        for (int t = 0; t < 4; t++) {
            const __nv_bfloat16* base = srcs[t] + (rowbase[t]) * GK + k0;
            cp_async16(st + t * GT_TILE + c0row * GP + c0col * 16,
                       base + (size_t)c0row * GK + c0col * 8);
            cp_async16(st + t * GT_TILE + c1row * GP + c1col * 16,
                       base + (size_t)c1row * GK + c1col * 8);
        }
        CP_COMMIT();
    };

    issue(0, 0);

    for (int kt = 0; kt < GK / 32; kt++) {
        const int s = kt & 1;
        CP_WAIT0();
        __syncthreads();
        if (kt + 1 < GK / 32) issue(s ^ 1, (kt + 1) * 32);

        const uint32_t st = sb + s * GT_STAGE;
#pragma unroll
        for (int ks = 0; ks < 2; ks++) {
            const uint32_t kb = ks * 32;
            uint32_t ah[2][4], al[2][4], bh2[4][4], bl2[4][4];
#pragma unroll
            for (int mi = 0; mi < 2; mi++) {
                const uint32_t ao = (uint32_t)(wm * 32 + mi * 16) * GP + kb + a_lane;
                ldmx4(ah[mi], st + ao);
                ldmx4(al[mi], st + GT_TILE + ao);
            }
#pragma unroll
            for (int bi = 0; bi < 4; bi++) {
                const uint32_t bo = (uint32_t)(wn * 64 + bi * 16) * GP + kb + b_lane;
                ldmx4(bh2[bi], st + 2 * GT_TILE + bo);
                ldmx4(bl2[bi], st + 3 * GT_TILE + bo);
            }
#pragma unroll
            for (int mi = 0; mi < 2; mi++)
#pragma unroll
                for (int bi = 0; bi < 4; bi++)
#pragma unroll
                    for (int t = 0; t < 2; t++) {
                        float* c = acc[mi][bi * 2 + t];
                        mma16816(c, ah[mi], bh2[bi][t * 2], bh2[bi][t * 2 + 1]);
                        mma16816(c, al[mi], bh2[bi][t * 2], bh2[bi][t * 2 + 1]);
                        mma16816(c, ah[mi], bl2[bi][t * 2], bl2[bi][t * 2 + 1]);
                    }
        }
    }

    const int mg = by * 128 + wm * 32 + (l >> 2);
    const int ng0 = bx * 128 + wn * 64 + (l & 3) * 2;

    if (epi_mode == 0) {
#pragma unroll
        for (int mi = 0; mi < 2; mi++) {
#pragma unroll
            for (int ni = 0; ni < 8; ni++) {
                const int n = ng0 + ni * 8;
                const float2 bv = *(const float2*)(bias + n);
                const int m0 = mg + mi * 16;
                *(float2*)(C + (size_t)m0 * n_dim + n) =
                    make_float2(acc[mi][ni][0] + bv.x, acc[mi][ni][1] + bv.y);
                *(float2*)(C + (size_t)(m0 + 8) * n_dim + n) =
                    make_float2(acc[mi][ni][2] + bv.x, acc[mi][ni][3] + bv.y);
            }
        }
    } else {
#pragma unroll
        for (int mi = 0; mi < 2; mi++) {
#pragma unroll
            for (int ni = 0; ni < 8; ni++) {
                const int n = ng0 + ni * 8;
                const int hh = n / 192;
                const int r = n - hh * 192;
                const int kind = r >> 6;
                const int d = r & 63;
                const float b0 = bias[n], b1 = bias[n + 1];
                const float scl = (kind == 0) ? SCALE_L2E : 1.0f;
                __nv_bfloat16* dsth = (kind == 0) ? qh : (kind == 1) ? kh : vh;
                __nv_bfloat16* dstl = (kind == 0) ? ql : (kind == 1) ? kl : vl;
#pragma unroll
                for (int hf = 0; hf < 2; hf++) {
                    const int m = mg + mi * 16 + hf * 8;
                    const int s = m >> 2, bb = m & 3;
                    const size_t off = ((size_t)(bb * NHEADS + hh) * S_LEN + s) * 64 + d;
                    uint32_t hiw, low;
                    split_hilo((acc[mi][ni][hf * 2 + 0] + b0) * scl,
                               (acc[mi][ni][hf * 2 + 1] + b1) * scl, hiw, low);
                    *(uint32_t*)(dsth + off) = hiw;
                    *(uint32_t*)(dstl + off) = low;
                }
            }
        }
    }
}

// ---------------------------------------------------------------------------
// Tensor-core flash attention v9: in-CTA split-KV. 512 threads = 2 halves of
// 8 warps; half z does k-tiles [z*16, z*16+16) with its own 3 smem stages and
// named barrier; smem merge at the end. Grid (16,64) -> 1024 CTAs / 148 SMs
// (tail 1.2% vs 15.6%). 1 CTA/SM.
// ---------------------------------------------------------------------------
#define A_ARR (64 * 144)                  // 9216 B per array
#define A_STAGE (4 * A_ARR)               // 36864 B (Kh,Kl,Vh,Vl)
#define A_SMEM (6 * A_STAGE)              // 221184 B -> 1 CTA/SM

__global__ void __launch_bounds__(512, 1)
attention_mma(const uint32_t* __restrict__ maskw,
              const __nv_bfloat16* __restrict__ Qh, const __nv_bfloat16* __restrict__ Ql,
              const __nv_bfloat16* __restrict__ Kh, const __nv_bfloat16* __restrict__ Kl,
              const __nv_bfloat16* __restrict__ Vh, const __nv_bfloat16* __restrict__ Vl,
              __nv_bfloat16* __restrict__ ctxh, __nv_bfloat16* __restrict__ ctxl) {
    extern __shared__ __align__(1024) char smem[];
    const uint32_t sb = smem_to_u32(smem);
    const int tid = threadIdx.x;
    const int z = tid >> 8;                     // half id 0/1
    const int t8 = tid & 255;                   // id within half
    const int w = t8 >> 5, l = t8 & 31;
    const int qt = blockIdx.x, bh = blockIdx.y;
    const int b = bh >> 4, h = bh & 15;
    const int q0 = qt * 128;
    const int kt0 = z * 16;
    const uint32_t hb = sb + (uint32_t)z * (3 * A_STAGE);   // this half's stage base
    const uint32_t* mrow_base = maskw + (size_t)((b << 9) | (qt << 5)) * 256 + t8;

#define HALF_BAR() asm volatile("bar.sync %0, 256;" :: "r"(1 + z) : "memory")

    // Q fragments straight from gmem (already scaled to log2 domain)
    uint32_t qfh[4][4], qfl[4][4];
    {
        const __nv_bfloat16* qgh = Qh + ((size_t)bh * S_LEN + q0 + w * 16) * 64;
        const __nv_bfloat16* qgl = Ql + ((size_t)bh * S_LEN + q0 + w * 16) * 64;
        const int r0 = l >> 2, k0 = 2 * (l & 3);
#pragma unroll
        for (int ks = 0; ks < 4; ks++) {
            const int kk = ks * 16 + k0;
            qfh[ks][0] = *(const uint32_t*)(qgh + r0 * 64 + kk);
            qfh[ks][1] = *(const uint32_t*)(qgh + (r0 + 8) * 64 + kk);
            qfh[ks][2] = *(const uint32_t*)(qgh + r0 * 64 + kk + 8);
            qfh[ks][3] = *(const uint32_t*)(qgh + (r0 + 8) * 64 + kk + 8);
            qfl[ks][0] = *(const uint32_t*)(qgl + r0 * 64 + kk);
            qfl[ks][1] = *(const uint32_t*)(qgl + (r0 + 8) * 64 + kk);
            qfl[ks][2] = *(const uint32_t*)(qgl + r0 * 64 + kk + 8);
            qfl[ks][3] = *(const uint32_t*)(qgl + (r0 + 8) * 64 + kk + 8);
        }
    }

    float acc[8][4];
#pragma unroll
    for (int i = 0; i < 8; i++)
#pragma unroll
        for (int j = 0; j < 4; j++) acc[i][j] = 0.0f;
    float m0 = -1e30f, m1 = -1e30f, lsum0 = 0.0f, lsum1 = 0.0f;

    auto issue = [&](int ktl) {
        const uint32_t st = hb + (uint32_t)(ktl % 3) * A_STAGE;
        const __nv_bfloat16* arrs[4] = {Kh, Kl, Vh, Vl};
        const int gkt = kt0 + ktl;
#pragma unroll
        for (int i = 0; i < 8; i++) {
            const int c = t8 + i * 256;
            const int arr = c >> 9;
            const int cc = c & 511;
            const int row = cc >> 3, col = cc & 7;
            cp_async16(st + arr * A_ARR + row * 144 + col * 16,
                       arrs[arr] + ((size_t)bh * S_LEN + gkt * 64 + row) * 64 + col * 8);
        }
        CP_COMMIT();
    };

    issue(0);
    issue(1);

    const uint32_t klane = (uint32_t)((l & 7) + ((l >> 4) & 1) * 8) * 144 + ((l >> 3) & 1) * 16;
    const uint32_t vlane = (uint32_t)((l & 7) + ((l >> 3) & 1) * 8) * 144 + ((l >> 4) & 1) * 16;

    uint32_t mw = mrow_base[(size_t)kt0 * 256];

    for (int ktl = 0; ktl < 16; ktl++) {
        if (ktl == 15) { CP_WAIT0(); } else { CP_WAIT1(); }
        HALF_BAR();
        if (ktl + 2 < 16) issue(ktl + 2);

        uint32_t mw_next = 0;
        if (ktl + 1 < 16) mw_next = mrow_base[(size_t)(kt0 + ktl + 1) * 256];

        const uint32_t st = hb + (uint32_t)(ktl % 3) * A_STAGE;

        // ---- scores = Q K^T, software-pipelined (16 steps) ----
        float sc[8][4];
#pragma unroll
        for (int i = 0; i < 8; i++) { sc[i][0] = sc[i][1] = sc[i][2] = sc[i][3] = 0.0f; }

        uint32_t kh4[2][4], kl4[2][4];
        {
            const uint32_t a0 = st + klane;
            ldmx4(kh4[0], a0);
            ldmx4(kl4[0], a0 + A_ARR);
        }
#pragma unroll
        for (int step = 0; step < 16; step++) {
            const int buf = step & 1;
            if (step < 15) {
                const int sn = step + 1;
                const uint32_t an = st + (uint32_t)((sn & 3) * 16) * 144 + (sn >> 2) * 32 + klane;
                ldmx4(kh4[buf ^ 1], an);
                ldmx4(kl4[buf ^ 1], an + A_ARR);
            }
            const int ks = step >> 2, nt2 = step & 3;
            mma16816(sc[2 * nt2],     qfh[ks], kh4[buf][0], kh4[buf][1]);
            mma16816(sc[2 * nt2],     qfl[ks], kh4[buf][0], kh4[buf][1]);
            mma16816(sc[2 * nt2],     qfh[ks], kl4[buf][0], kl4[buf][1]);
            mma16816(sc[2 * nt2 + 1], qfh[ks], kh4[buf][2], kh4[buf][3]);
            mma16816(sc[2 * nt2 + 1], qfl[ks], kh4[buf][2], kh4[buf][3]);
            mma16816(sc[2 * nt2 + 1], qfh[ks], kl4[buf][2], kl4[buf][3]);
        }

        // ---- mask (log2 domain; FSEL only) ----
#pragma unroll
        for (int nt = 0; nt < 8; nt++) {
            if ((mw >> (nt * 4 + 0)) & 1) sc[nt][0] = MASK_L2;
            if ((mw >> (nt * 4 + 1)) & 1) sc[nt][1] = MASK_L2;
            if ((mw >> (nt * 4 + 2)) & 1) sc[nt][2] = MASK_L2;
            if ((mw >> (nt * 4 + 3)) & 1) sc[nt][3] = MASK_L2;
        }
        mw = mw_next;

        // ---- online softmax (log2 domain, ex2 on MUFU) ----
        float mx0 = sc[0][0], mx1 = sc[0][2];
#pragma unroll
        for (int nt = 0; nt < 8; nt++) {
            mx0 = fmaxf(mx0, fmaxf(sc[nt][0], sc[nt][1]));
            mx1 = fmaxf(mx1, fmaxf(sc[nt][2], sc[nt][3]));
        }
        mx0 = fmaxf(mx0, __shfl_xor_sync(0xFFFFFFFFu, mx0, 1));
        mx0 = fmaxf(mx0, __shfl_xor_sync(0xFFFFFFFFu, mx0, 2));
        mx1 = fmaxf(mx1, __shfl_xor_sync(0xFFFFFFFFu, mx1, 1));
        mx1 = fmaxf(mx1, __shfl_xor_sync(0xFFFFFFFFu, mx1, 2));

        const float nm0 = fmaxf(m0, mx0), nm1 = fmaxf(m1, mx1);
        const float cr0 = ex2(m0 - nm0), cr1 = ex2(m1 - nm1);
        m0 = nm0; m1 = nm1;

        float s0 = 0.0f, s1 = 0.0f;
#pragma unroll
        for (int nt = 0; nt < 8; nt++) {
            sc[nt][0] = ex2(sc[nt][0] - nm0); s0 += sc[nt][0];
            sc[nt][1] = ex2(sc[nt][1] - nm0); s0 += sc[nt][1];
            sc[nt][2] = ex2(sc[nt][2] - nm1); s1 += sc[nt][2];
            sc[nt][3] = ex2(sc[nt][3] - nm1); s1 += sc[nt][3];
        }
        s0 += __shfl_xor_sync(0xFFFFFFFFu, s0, 1);
        s0 += __shfl_xor_sync(0xFFFFFFFFu, s0, 2);
        s1 += __shfl_xor_sync(0xFFFFFFFFu, s1, 1);
        s1 += __shfl_xor_sync(0xFFFFFFFFu, s1, 2);
        lsum0 = lsum0 * cr0 + s0;
        lsum1 = lsum1 * cr1 + s1;
#pragma unroll
        for (int nt = 0; nt < 8; nt++) {
            acc[nt][0] *= cr0; acc[nt][1] *= cr0;
            acc[nt][2] *= cr1; acc[nt][3] *= cr1;
        }

        // ---- ctx += P V, two halves, software-pipelined V loads ----
#pragma unroll
        for (int half = 0; half < 2; half++) {
            uint32_t ph[2][4], pl[2][4];
#pragma unroll
            for (int k2 = 0; k2 < 2; k2++) {
                const int kt16 = half * 2 + k2;
                split_hilo(sc[2 * kt16][0],     sc[2 * kt16][1],     ph[k2][0], pl[k2][0]);
                split_hilo(sc[2 * kt16][2],     sc[2 * kt16][3],     ph[k2][1], pl[k2][1]);
                split_hilo(sc[2 * kt16 + 1][0], sc[2 * kt16 + 1][1], ph[k2][2], pl[k2][2]);
                split_hilo(sc[2 * kt16 + 1][2], sc[2 * kt16 + 1][3], ph[k2][3], pl[k2][3]);
            }
            uint32_t vh4[2][4], vl4[2][4];
            {
                const uint32_t a0 = st + 2 * A_ARR + (uint32_t)(half * 2 * 16) * 144 + vlane;
                ldmx4t(vh4[0], a0);
                ldmx4t(vl4[0], a0 + A_ARR);
            }
#pragma unroll
            for (int step = 0; step < 8; step++) {
                const int buf = step & 1;
                if (step < 7) {
                    const int sn = step + 1;
                    const uint32_t an = st + 2 * A_ARR
                        + (uint32_t)((half * 2 + (sn >> 2)) * 16) * 144 + (sn & 3) * 32 + vlane;
                    ldmx4t(vh4[buf ^ 1], an);
                    ldmx4t(vl4[buf ^ 1], an + A_ARR);
                }
                const int k2 = step >> 2, db = step & 3;
                float* c0 = acc[2 * db];
                float* c1 = acc[2 * db + 1];
                mma16816(c0, ph[k2], vh4[buf][0], vh4[buf][1]);
                mma16816(c0, pl[k2], vh4[buf][0], vh4[buf][1]);
                mma16816(c0, ph[k2], vl4[buf][0], vl4[buf][1]);
                mma16816(c1, ph[k2], vh4[buf][2], vh4[buf][3]);
                mma16816(c1, pl[k2], vh4[buf][2], vh4[buf][3]);
                mma16816(c1, ph[k2], vl4[buf][2], vl4[buf][3]);
            }
        }
    }

    // ---- in-smem merge of the two KV halves ----
    __syncthreads();                       // all compute done; stages reusable
    float* scr = (float*)smem;             // 256 threads x 36 floats = 36 KB
    if (z == 1) {
        float* s = scr + (size_t)t8 * 36;
#pragma unroll
        for (int nt = 0; nt < 8; nt++) {
            s[nt * 4 + 0] = acc[nt][0]; s[nt * 4 + 1] = acc[nt][1];
            s[nt * 4 + 2] = acc[nt][2]; s[nt * 4 + 3] = acc[nt][3];
        }
        s[32] = m0; s[33] = lsum0; s[34] = m1; s[35] = lsum1;
    }
    __syncthreads();
    if (z == 0) {
        const float* s = scr + (size_t)t8 * 36;
        const float pm0 = s[32], pl0 = s[33], pm1 = s[34], pl1 = s[35];
        const float M0 = fmaxf(m0, pm0), M1 = fmaxf(m1, pm1);
        const float wa0 = ex2(m0 - M0), wb0 = ex2(pm0 - M0);
        const float wa1 = ex2(m1 - M1), wb1 = ex2(pm1 - M1);
        const float iL0 = 1.0f / (lsum0 * wa0 + pl0 * wb0);
        const float iL1 = 1.0f / (lsum1 * wa1 + pl1 * wb1);
        const float fa0 = wa0 * iL0, fb0 = wb0 * iL0;
        const float fa1 = wa1 * iL1, fb1 = wb1 * iL1;

        const int srow = q0 + w * 16 + (l >> 2);
        const int colb = h * 64 + 2 * (l & 3);
#pragma unroll
        for (int nt = 0; nt < 8; nt++) {
            const int col = colb + nt * 8;
            const float c0 = acc[nt][0] * fa0 + s[nt * 4 + 0] * fb0;
            const float c1 = acc[nt][1] * fa0 + s[nt * 4 + 1] * fb0;
            const float c2 = acc[nt][2] * fa1 + s[nt * 4 + 2] * fb1;
            const float c3 = acc[nt][3] * fa1 + s[nt * 4 + 3] * fb1;
            uint32_t hiw, low;
            split_hilo(c0, c1, hiw, low);
            const size_t off0 = ((size_t)srow * 4 + b) * HID + col;
            *(uint32_t*)(ctxh + off0) = hiw;
            *(uint32_t*)(ctxl + off0) = low;
            split_hilo(c2, c3, hiw, low);
            const size_t off1 = ((size_t)(srow + 8) * 4 + b) * HID + col;
            *(uint32_t*)(ctxh + off1) = hiw;
            *(uint32_t*)(ctxl + off1) = low;
        }
    }
#undef HALF_BAR
}

// ---------------------------------------------------------------------------
// Launch
// ---------------------------------------------------------------------------
extern "C" void kernel_launch(void* const* d_in, const int* in_sizes, int n_in,
                              void* d_out, int out_size) {
    const float* hs      = (const float*)d_in[0];
    const void*  mask    = d_in[1];
    const float* W_qkv   = (const float*)d_in[2];
    const float* b_qkv   = (const float*)d_in[3];
    const float* W_dense = (const float*)d_in[4];
    const float* b_dense = (const float*)d_in[5];
    float* out = (float*)d_out;

    __nv_bfloat16 *pAh, *pAl, *pWqh, *pWql, *pWdh, *pWdl;
    __nv_bfloat16 *Qh, *Ql, *Kh, *Kl, *Vh, *Vl;
    uint32_t* maskbits;
    cudaGetSymbolAddress((void**)&pAh, g_pA_hi);
    cudaGetSymbolAddress((void**)&pAl, g_pA_lo);
    cudaGetSymbolAddress((void**)&pWqh, g_pWq_hi);
    cudaGetSymbolAddress((void**)&pWql, g_pWq_lo);
    cudaGetSymbolAddress((void**)&pWdh, g_pWd_hi);
    cudaGetSymbolAddress((void**)&pWdl, g_pWd_lo);
    cudaGetSymbolAddress((void**)&Qh, g_Qh);
    cudaGetSymbolAddress((void**)&Ql, g_Ql);
    cudaGetSymbolAddress((void**)&Kh, g_Kh);
    cudaGetSymbolAddress((void**)&Kl, g_Kl);
    cudaGetSymbolAddress((void**)&Vh, g_Vh);
    cudaGetSymbolAddress((void**)&Vl, g_Vl);
    cudaGetSymbolAddress((void**)&maskbits, g_mask_bits);

    cudaFuncSetAttribute(gemm_mma, cudaFuncAttributeMaxDynamicSharedMemorySize, GT_SMEM);
    cudaFuncSetAttribute(attention_mma, cudaFuncAttributeMaxDynamicSharedMemorySize, A_SMEM);

    // 0) mask dtype + fragment-layout bit conversion
    detect_mask_dtype<<<1, 32>>>((const int*)mask);
    convert_mask_frag<<<BATCH * 16 * 32, 256>>>(mask, maskbits);

    // 1) pack hs + W_qkv + W_dense
    pack_hilo<<<(M_ROWS * HID / 4) / 256, 256>>>(hs, pAh, pAl);
    pack_hilo<<<(QKV_N * HID / 4) / 256, 256>>>(W_qkv, pWqh, pWql);
    pack_hilo<<<(HID * HID / 4) / 256, 256>>>(W_dense, pWdh, pWdl);

    // 2) QKV GEMM -> split bf16 hi/lo Q/K/V (Q pre-scaled to log2 domain)
    gemm_mma<<<dim3(QKV_N / 128, M_ROWS / 128), 256, GT_SMEM>>>(
        pAh, pAl, pWqh, pWql, b_qkv, nullptr, QKV_N, 1, Qh, Ql, Kh, Kl, Vh, Vl);

    // 3) in-CTA split-KV flash attention -> ctx hi/lo (into pA buffers)
    attention_mma<<<dim3(S_LEN / 128, BATCH * NHEADS), 512, A_SMEM>>>(
        maskbits, Qh, Ql, Kh, Kl, Vh, Vl, pAh, pAl);

    // 4) dense GEMM -> out
    gemm_mma<<<dim3(HID / 128, M_ROWS / 128), 256, GT_SMEM>>>(
        pAh, pAl, pWdh, pWdl, b_dense, out, HID, 0,
        nullptr, nullptr, nullptr, nullptr, nullptr, nullptr);
}

// round 17
// speedup vs baseline: 1.0110x; 1.0110x over previous
#include <cuda_runtime.h>
#include <cuda_bf16.h>
#include <math.h>
#include <stdint.h>

#define S_LEN 2048
#define BATCH 4
#define HID 1024
#define NHEADS 16
#define HDIM 64
#define M_ROWS (S_LEN * BATCH)   // 8192
#define QKV_N (3 * HID)          // 3072
#define GK HID                   // K dim of both GEMMs = 1024
#define SCALE_L2E 0.18033688011112043f   // 0.125 * log2(e)  (pre-folded into Q)
#define MASK_L2  (-14426.950408889634f)  // -10000 * log2(e)

// ---------------- scratch (allocation-free: device globals) ----------------
__device__ int g_mask_is_i32;
__device__ uint32_t g_mask_bits[(size_t)BATCH * 16 * 32 * 256];   // 2 MB

#define QKV_ELEMS ((size_t)64 * S_LEN * HDIM)
__device__ __align__(16) __nv_bfloat16 g_Qh[QKV_ELEMS], g_Ql[QKV_ELEMS];
__device__ __align__(16) __nv_bfloat16 g_Kh[QKV_ELEMS], g_Kl[QKV_ELEMS];
__device__ __align__(16) __nv_bfloat16 g_Vh[QKV_ELEMS], g_Vl[QKV_ELEMS];

__device__ __align__(16) __nv_bfloat16 g_pA_hi[(size_t)M_ROWS * HID];
__device__ __align__(16) __nv_bfloat16 g_pA_lo[(size_t)M_ROWS * HID];
__device__ __align__(16) __nv_bfloat16 g_pWq_hi[(size_t)QKV_N * HID];
__device__ __align__(16) __nv_bfloat16 g_pWq_lo[(size_t)QKV_N * HID];
__device__ __align__(16) __nv_bfloat16 g_pWd_hi[(size_t)HID * HID];
__device__ __align__(16) __nv_bfloat16 g_pWd_lo[(size_t)HID * HID];

// ---------------- helpers ----------------
__device__ __forceinline__ uint32_t smem_to_u32(const void* p) {
    uint32_t a;
    asm("{ .reg .u64 t; cvta.to.shared.u64 t, %1; cvt.u32.u64 %0, t; }" : "=r"(a) : "l"(p));
    return a;
}
__device__ __forceinline__ void cp_async16(uint32_t dst, const void* src) {
    asm volatile("cp.async.cg.shared.global [%0], [%1], 16;" :: "r"(dst), "l"(src));
}
#define CP_COMMIT() asm volatile("cp.async.commit_group;" ::: "memory")
#define CP_WAIT0()  asm volatile("cp.async.wait_group 0;" ::: "memory")
#define CP_WAIT1()  asm volatile("cp.async.wait_group 1;" ::: "memory")

__device__ __forceinline__ void ldmx4(uint32_t* r, uint32_t addr) {
    asm volatile("ldmatrix.sync.aligned.m8n8.x4.shared.b16 {%0,%1,%2,%3}, [%4];"
                 : "=r"(r[0]), "=r"(r[1]), "=r"(r[2]), "=r"(r[3]) : "r"(addr));
}
__device__ __forceinline__ void ldmx4t(uint32_t* r, uint32_t addr) {
    asm volatile("ldmatrix.sync.aligned.m8n8.x4.trans.shared.b16 {%0,%1,%2,%3}, [%4];"
                 : "=r"(r[0]), "=r"(r[1]), "=r"(r[2]), "=r"(r[3]) : "r"(addr));
}
__device__ __forceinline__ void mma16816(float* c, const uint32_t* a, uint32_t b0, uint32_t b1) {
    asm volatile(
        "mma.sync.aligned.m16n8k16.row.col.f32.bf16.bf16.f32 "
        "{%0,%1,%2,%3}, {%4,%5,%6,%7}, {%8,%9}, {%0,%1,%2,%3};"
        : "+f"(c[0]), "+f"(c[1]), "+f"(c[2]), "+f"(c[3])
        : "r"(a[0]), "r"(a[1]), "r"(a[2]), "r"(a[3]), "r"(b0), "r"(b1));
}
__device__ __forceinline__ uint32_t packbf2(float vhigh, float vlow) {
    uint32_t r;
    asm("cvt.rn.bf16x2.f32 %0, %1, %2;" : "=r"(r) : "f"(vhigh), "f"(vlow));
    return r;
}
__device__ __forceinline__ void split_hilo(float v0, float v1, uint32_t& hi, uint32_t& lo) {
    hi = packbf2(v1, v0);
    const float h0 = __int_as_float(hi << 16);
    const float h1 = __int_as_float(hi & 0xFFFF0000u);
    lo = packbf2(v1 - h1, v0 - h0);
}
__device__ __forceinline__ float ex2(float x) {
    float y;
    asm("ex2.approx.f32 %0, %1;" : "=f"(y) : "f"(x));
    return y;
}

// ---------------------------------------------------------------------------
// Mask dtype detect
// ---------------------------------------------------------------------------
__global__ void detect_mask_dtype(const int* __restrict__ m) {
    int bad = 0;
#pragma unroll
    for (int i = 0; i < 32; i++) {
        unsigned v = (unsigned)m[threadIdx.x * 32 + i];
        bad |= (v > 1u);
    }
    unsigned any = __ballot_sync(0xFFFFFFFFu, bad);
    if (threadIdx.x == 0) g_mask_is_i32 = (any == 0) ? 1 : 0;
}

// ---------------------------------------------------------------------------
// Mask -> fragment-layout bitwords (verified in R11/R12)
// ---------------------------------------------------------------------------
__global__ void __launch_bounds__(256)
convert_mask_frag(const void* __restrict__ raw, uint32_t* __restrict__ out) {
    __shared__ unsigned char mt[128 * 64];
    const int blk = blockIdx.x;
    const int kt = blk & 31, qt = (blk >> 5) & 15, b = blk >> 9;
    const int tid = threadIdx.x;
    const size_t base = ((size_t)b * S_LEN + qt * 128) * S_LEN + kt * 64;

    if (g_mask_is_i32) {
        const int* m = (const int*)raw;
#pragma unroll
        for (int i = 0; i < 8; i++) {
            const int c = tid + i * 256;
            const int row = c >> 4, c4 = (c & 15) * 4;
            const int4 v = *(const int4*)(m + base + (size_t)row * S_LEN + c4);
            mt[row * 64 + c4 + 0] = (unsigned char)v.x;
            mt[row * 64 + c4 + 1] = (unsigned char)v.y;
            mt[row * 64 + c4 + 2] = (unsigned char)v.z;
            mt[row * 64 + c4 + 3] = (unsigned char)v.w;
        }
    } else {
        const unsigned char* m = (const unsigned char*)raw;
#pragma unroll
        for (int i = 0; i < 2; i++) {
            const int c = tid + i * 256;
            const int row = c >> 2, col = (c & 3) * 16;
            *(uint4*)&mt[row * 64 + col] =
                *(const uint4*)(m + base + (size_t)row * S_LEN + col);
        }
    }
    __syncthreads();

    const int g = tid >> 5, l = tid & 31;
    const int r0 = g * 16 + (l >> 2);
    const int c0 = 2 * (l & 3);
    uint32_t word = 0;
#pragma unroll
    for (int nt = 0; nt < 8; nt++) {
#pragma unroll
        for (int j = 0; j < 4; j++) {
            const int r = r0 + ((j >> 1) ? 8 : 0);
            const int c = c0 + nt * 8 + (j & 1);
            word |= (mt[r * 64 + c] ? 1u : 0u) << (nt * 4 + j);
        }
    }
    out[(size_t)blk * 256 + tid] = word;
}

// ---------------------------------------------------------------------------
// Fused pack: hs -> pA, W_qkv -> pWq, W_dense -> pWd in ONE launch.
// Thread ranges (in float4 units): hs 2,097,152 | Wq 786,432 | Wd 262,144.
// ---------------------------------------------------------------------------
#define PK_HS  (M_ROWS * HID / 4)           // 2097152
#define PK_WQ  (QKV_N * HID / 4)            // 786432
#define PK_ALL (PK_HS + PK_WQ + (HID * HID / 4))

__global__ void __launch_bounds__(256)
pack_all(const float* __restrict__ hs, const float* __restrict__ wq,
         const float* __restrict__ wd,
         __nv_bfloat16* __restrict__ pAh, __nv_bfloat16* __restrict__ pAl,
         __nv_bfloat16* __restrict__ pWqh, __nv_bfloat16* __restrict__ pWql,
         __nv_bfloat16* __restrict__ pWdh, __nv_bfloat16* __restrict__ pWdl) {
    const size_t idx = (size_t)blockIdx.x * 256 + threadIdx.x;
    const float* src;
    __nv_bfloat16 *hi, *lo;
    size_t e;
    if (idx < PK_HS) {
        src = hs; hi = pAh; lo = pAl; e = idx;
    } else if (idx < PK_HS + PK_WQ) {
        src = wq; hi = pWqh; lo = pWql; e = idx - PK_HS;
    } else {
        src = wd; hi = pWdh; lo = pWdl; e = idx - PK_HS - PK_WQ;
    }
    const float4 v = *(const float4*)(src + e * 4);
    uint32_t h0, l0, h1, l1;
    split_hilo(v.x, v.y, h0, l0);
    split_hilo(v.z, v.w, h1, l1);
    *(uint2*)(hi + e * 4) = make_uint2(h0, h1);
    *(uint2*)(lo + e * 4) = make_uint2(l0, l1);
}

// ---------------------------------------------------------------------------
// bf16 hi/lo GEMM via mma.sync — 2 CTAs/SM, ONE sync per iter.
// epi_mode 1 writes Q pre-scaled by SCALE_L2E.
// ---------------------------------------------------------------------------
#define GP 80
#define GT_TILE (128 * GP)
#define GT_STAGE (4 * GT_TILE)
#define GT_SMEM (2 * GT_STAGE)

__global__ void __launch_bounds__(256, 2)
gemm_mma(const __nv_bfloat16* __restrict__ Ahi, const __nv_bfloat16* __restrict__ Alo,
         const __nv_bfloat16* __restrict__ Bhi, const __nv_bfloat16* __restrict__ Blo,
         const float* __restrict__ bias, float* __restrict__ C, int n_dim, int epi_mode,
         __nv_bfloat16* qh, __nv_bfloat16* ql, __nv_bfloat16* kh,
         __nv_bfloat16* kl, __nv_bfloat16* vh, __nv_bfloat16* vl) {
    extern __shared__ __align__(1024) char smem[];
    const uint32_t sb = smem_to_u32(smem);
    const int tid = threadIdx.x;
    const int bx = blockIdx.x, by = blockIdx.y;
    const int w = tid >> 5, l = tid & 31;
    const int wm = w >> 1, wn = w & 1;

    const int c0row = tid >> 2,        c0col = tid & 3;
    const int c1row = (tid + 256) >> 2, c1col = (tid + 256) & 3;

    const __nv_bfloat16* srcs[4] = {Ahi, Alo, Bhi, Blo};
    const size_t rowbase[4] = {(size_t)by * 128, (size_t)by * 128,
                               (size_t)bx * 128, (size_t)bx * 128};

    float acc[2][8][4];
#pragma unroll
    for (int i = 0; i < 2; i++)
#pragma unroll
        for (int j = 0; j < 8; j++)
#pragma unroll
            for (int q = 0; q < 4; q++) acc[i][j][q] = 0.0f;

    const uint32_t a_lane = (uint32_t)(l & 15) * GP + ((l >> 4) & 1) * 16;
    const uint32_t b_lane = (uint32_t)((l & 7) + ((l >> 4) & 1) * 8) * GP + ((l >> 3) & 1) * 16;

    auto issue = [&](int s, int k0) {
        const uint32_t st = sb + s * GT_STAGE;
#pragma unroll
        for (int t = 0; t < 4; t++) {
            const __nv_bfloat16* base = srcs[t] + (rowbase[t]) * GK + k0;
            cp_async16(st + t * GT_TILE + c0row * GP + c0col * 16,
                       base + (size_t)c0row * GK + c0col * 8);
            cp_async16(st + t * GT_TILE + c1row * GP + c1col * 16,
                       base + (size_t)c1row * GK + c1col * 8);
        }
        CP_COMMIT();
    };

    issue(0, 0);

    for (int kt = 0; kt < GK / 32; kt++) {
        const int s = kt & 1;
        CP_WAIT0();
        __syncthreads();
        if (kt + 1 < GK / 32) issue(s ^ 1, (kt + 1) * 32);

        const uint32_t st = sb + s * GT_STAGE;
#pragma unroll
        for (int ks = 0; ks < 2; ks++) {
            const uint32_t kb = ks * 32;
            uint32_t ah[2][4], al[2][4], bh2[4][4], bl2[4][4];
#pragma unroll
            for (int mi = 0; mi < 2; mi++) {
                const uint32_t ao = (uint32_t)(wm * 32 + mi * 16) * GP + kb + a_lane;
                ldmx4(ah[mi], st + ao);
                ldmx4(al[mi], st + GT_TILE + ao);
            }
#pragma unroll
            for (int bi = 0; bi < 4; bi++) {
                const uint32_t bo = (uint32_t)(wn * 64 + bi * 16) * GP + kb + b_lane;
                ldmx4(bh2[bi], st + 2 * GT_TILE + bo);
                ldmx4(bl2[bi], st + 3 * GT_TILE + bo);
            }
#pragma unroll
            for (int mi = 0; mi < 2; mi++)
#pragma unroll
                for (int bi = 0; bi < 4; bi++)
#pragma unroll
                    for (int t = 0; t < 2; t++) {
                        float* c = acc[mi][bi * 2 + t];
                        mma16816(c, ah[mi], bh2[bi][t * 2], bh2[bi][t * 2 + 1]);
                        mma16816(c, al[mi], bh2[bi][t * 2], bh2[bi][t * 2 + 1]);
                        mma16816(c, ah[mi], bl2[bi][t * 2], bl2[bi][t * 2 + 1]);
                    }
        }
    }

    const int mg = by * 128 + wm * 32 + (l >> 2);
    const int ng0 = bx * 128 + wn * 64 + (l & 3) * 2;

    if (epi_mode == 0) {
#pragma unroll
        for (int mi = 0; mi < 2; mi++) {
#pragma unroll
            for (int ni = 0; ni < 8; ni++) {
                const int n = ng0 + ni * 8;
                const float2 bv = *(const float2*)(bias + n);
                const int m0 = mg + mi * 16;
                *(float2*)(C + (size_t)m0 * n_dim + n) =
                    make_float2(acc[mi][ni][0] + bv.x, acc[mi][ni][1] + bv.y);
                *(float2*)(C + (size_t)(m0 + 8) * n_dim + n) =
                    make_float2(acc[mi][ni][2] + bv.x, acc[mi][ni][3] + bv.y);
            }
        }
    } else {
#pragma unroll
        for (int mi = 0; mi < 2; mi++) {
#pragma unroll
            for (int ni = 0; ni < 8; ni++) {
                const int n = ng0 + ni * 8;
                const int hh = n / 192;
                const int r = n - hh * 192;
                const int kind = r >> 6;
                const int d = r & 63;
                const float b0 = bias[n], b1 = bias[n + 1];
                const float scl = (kind == 0) ? SCALE_L2E : 1.0f;
                __nv_bfloat16* dsth = (kind == 0) ? qh : (kind == 1) ? kh : vh;
                __nv_bfloat16* dstl = (kind == 0) ? ql : (kind == 1) ? kl : vl;
#pragma unroll
                for (int hf = 0; hf < 2; hf++) {
                    const int m = mg + mi * 16 + hf * 8;
                    const int s = m >> 2, bb = m & 3;
                    const size_t off = ((size_t)(bb * NHEADS + hh) * S_LEN + s) * 64 + d;
                    uint32_t hiw, low;
                    split_hilo((acc[mi][ni][hf * 2 + 0] + b0) * scl,
                               (acc[mi][ni][hf * 2 + 1] + b1) * scl, hiw, low);
                    *(uint32_t*)(dsth + off) = hiw;
                    *(uint32_t*)(dstl + off) = low;
                }
            }
        }
    }
}

// ---------------------------------------------------------------------------
// Tensor-core flash attention (R12/R15 plateau core): 3-stage cp.async,
// one sync/iter, bitmask, 2 CTAs/SM, 8 warps. cp.async stages issued BEFORE
// Q-fragment LDGs so DMA overlaps Q latency.
// ---------------------------------------------------------------------------
#define A_ARR (64 * 144)                  // 9216 B per array
#define A_STAGE (4 * A_ARR)               // 36864 B (Kh,Kl,Vh,Vl)
#define A_SMEM (3 * A_STAGE)              // 110592 B -> 2 CTAs/SM

__global__ void __launch_bounds__(256, 2)
attention_mma(const uint32_t* __restrict__ maskw,
              const __nv_bfloat16* __restrict__ Qh, const __nv_bfloat16* __restrict__ Ql,
              const __nv_bfloat16* __restrict__ Kh, const __nv_bfloat16* __restrict__ Kl,
              const __nv_bfloat16* __restrict__ Vh, const __nv_bfloat16* __restrict__ Vl,
              __nv_bfloat16* __restrict__ ctxh, __nv_bfloat16* __restrict__ ctxl) {
    extern __shared__ __align__(1024) char smem[];
    const uint32_t sb = smem_to_u32(smem);
    const int tid = threadIdx.x, w = tid >> 5, l = tid & 31;
    const int qt = blockIdx.x, bh = blockIdx.y;
    const int b = bh >> 4, h = bh & 15;
    const int q0 = qt * 128;
    const uint32_t* mrow_base = maskw + (size_t)((b << 9) | (qt << 5)) * 256 + tid;

    auto issue = [&](int kt) {
        const uint32_t st = sb + (uint32_t)(kt % 3) * A_STAGE;
        const __nv_bfloat16* arrs[4] = {Kh, Kl, Vh, Vl};
#pragma unroll
        for (int i = 0; i < 8; i++) {
            const int c = tid + i * 256;
            const int arr = c >> 9;
            const int cc = c & 511;
            const int row = cc >> 3, col = cc & 7;
            cp_async16(st + arr * A_ARR + row * 144 + col * 16,
                       arrs[arr] + ((size_t)bh * S_LEN + kt * 64 + row) * 64 + col * 8);
        }
        CP_COMMIT();
    };

    // start DMA first, then load Q fragments under it
    issue(0);
    issue(1);

    uint32_t qfh[4][4], qfl[4][4];
    {
        const __nv_bfloat16* qgh = Qh + ((size_t)bh * S_LEN + q0 + w * 16) * 64;
        const __nv_bfloat16* qgl = Ql + ((size_t)bh * S_LEN + q0 + w * 16) * 64;
        const int r0 = l >> 2, k0 = 2 * (l & 3);
#pragma unroll
        for (int ks = 0; ks < 4; ks++) {
            const int kk = ks * 16 + k0;
            qfh[ks][0] = *(const uint32_t*)(qgh + r0 * 64 + kk);
            qfh[ks][1] = *(const uint32_t*)(qgh + (r0 + 8) * 64 + kk);
            qfh[ks][2] = *(const uint32_t*)(qgh + r0 * 64 + kk + 8);
            qfh[ks][3] = *(const uint32_t*)(qgh + (r0 + 8) * 64 + kk + 8);
            qfl[ks][0] = *(const uint32_t*)(qgl + r0 * 64 + kk);
            qfl[ks][1] = *(const uint32_t*)(qgl + (r0 + 8) * 64 + kk);
            qfl[ks][2] = *(const uint32_t*)(qgl + r0 * 64 + kk + 8);
            qfl[ks][3] = *(const uint32_t*)(qgl + (r0 + 8) * 64 + kk + 8);
        }
    }

    float acc[8][4];
#pragma unroll
    for (int i = 0; i < 8; i++)
#pragma unroll
        for (int j = 0; j < 4; j++) acc[i][j] = 0.0f;
    float m0 = -1e30f, m1 = -1e30f, lsum0 = 0.0f, lsum1 = 0.0f;

    const uint32_t klane = (uint32_t)((l & 7) + ((l >> 4) & 1) * 8) * 144 + ((l >> 3) & 1) * 16;
    const uint32_t vlane = (uint32_t)((l & 7) + ((l >> 3) & 1) * 8) * 144 + ((l >> 4) & 1) * 16;

    uint32_t mw = mrow_base[0];

    for (int kt = 0; kt < 32; kt++) {
        if (kt == 31) { CP_WAIT0(); } else { CP_WAIT1(); }
        __syncthreads();
        if (kt + 2 < 32) issue(kt + 2);

        uint32_t mw_next = 0;
        if (kt + 1 < 32) mw_next = mrow_base[(size_t)(kt + 1) * 256];

        const uint32_t st = sb + (uint32_t)(kt % 3) * A_STAGE;

        // ---- scores = Q K^T, software-pipelined (16 steps) ----
        float sc[8][4];
#pragma unroll
        for (int i = 0; i < 8; i++) { sc[i][0] = sc[i][1] = sc[i][2] = sc[i][3] = 0.0f; }

        uint32_t kh4[2][4], kl4[2][4];
        {
            const uint32_t a0 = st + klane;
            ldmx4(kh4[0], a0);
            ldmx4(kl4[0], a0 + A_ARR);
        }
#pragma unroll
        for (int step = 0; step < 16; step++) {
            const int buf = step & 1;
            if (step < 15) {
                const int sn = step + 1;
                const uint32_t an = st + (uint32_t)((sn & 3) * 16) * 144 + (sn >> 2) * 32 + klane;
                ldmx4(kh4[buf ^ 1], an);
                ldmx4(kl4[buf ^ 1], an + A_ARR);
            }
            const int ks = step >> 2, nt2 = step & 3;
            mma16816(sc[2 * nt2],     qfh[ks], kh4[buf][0], kh4[buf][1]);
            mma16816(sc[2 * nt2],     qfl[ks], kh4[buf][0], kh4[buf][1]);
            mma16816(sc[2 * nt2],     qfh[ks], kl4[buf][0], kl4[buf][1]);
            mma16816(sc[2 * nt2 + 1], qfh[ks], kh4[buf][2], kh4[buf][3]);
            mma16816(sc[2 * nt2 + 1], qfl[ks], kh4[buf][2], kh4[buf][3]);
            mma16816(sc[2 * nt2 + 1], qfh[ks], kl4[buf][2], kl4[buf][3]);
        }

        // ---- mask (log2 domain; FSEL only) ----
#pragma unroll
        for (int nt = 0; nt < 8; nt++) {
            if ((mw >> (nt * 4 + 0)) & 1) sc[nt][0] = MASK_L2;
            if ((mw >> (nt * 4 + 1)) & 1) sc[nt][1] = MASK_L2;
            if ((mw >> (nt * 4 + 2)) & 1) sc[nt][2] = MASK_L2;
            if ((mw >> (nt * 4 + 3)) & 1) sc[nt][3] = MASK_L2;
        }
        mw = mw_next;

        // ---- online softmax (log2 domain, ex2 on MUFU) ----
        float mx0 = sc[0][0], mx1 = sc[0][2];
#pragma unroll
        for (int nt = 0; nt < 8; nt++) {
            mx0 = fmaxf(mx0, fmaxf(sc[nt][0], sc[nt][1]));
            mx1 = fmaxf(mx1, fmaxf(sc[nt][2], sc[nt][3]));
        }
        mx0 = fmaxf(mx0, __shfl_xor_sync(0xFFFFFFFFu, mx0, 1));
        mx0 = fmaxf(mx0, __shfl_xor_sync(0xFFFFFFFFu, mx0, 2));
        mx1 = fmaxf(mx1, __shfl_xor_sync(0xFFFFFFFFu, mx1, 1));
        mx1 = fmaxf(mx1, __shfl_xor_sync(0xFFFFFFFFu, mx1, 2));

        const float nm0 = fmaxf(m0, mx0), nm1 = fmaxf(m1, mx1);
        const float cr0 = ex2(m0 - nm0), cr1 = ex2(m1 - nm1);
        m0 = nm0; m1 = nm1;

        float s0 = 0.0f, s1 = 0.0f;
#pragma unroll
        for (int nt = 0; nt < 8; nt++) {
            sc[nt][0] = ex2(sc[nt][0] - nm0); s0 += sc[nt][0];
            sc[nt][1] = ex2(sc[nt][1] - nm0); s0 += sc[nt][1];
            sc[nt][2] = ex2(sc[nt][2] - nm1); s1 += sc[nt][2];
            sc[nt][3] = ex2(sc[nt][3] - nm1); s1 += sc[nt][3];
        }
        s0 += __shfl_xor_sync(0xFFFFFFFFu, s0, 1);
        s0 += __shfl_xor_sync(0xFFFFFFFFu, s0, 2);
        s1 += __shfl_xor_sync(0xFFFFFFFFu, s1, 1);
        s1 += __shfl_xor_sync(0xFFFFFFFFu, s1, 2);
        lsum0 = lsum0 * cr0 + s0;
        lsum1 = lsum1 * cr1 + s1;
#pragma unroll
        for (int nt = 0; nt < 8; nt++) {
            acc[nt][0] *= cr0; acc[nt][1] *= cr0;
            acc[nt][2] *= cr1; acc[nt][3] *= cr1;
        }

        // ---- ctx += P V, two halves, software-pipelined V loads ----
#pragma unroll
        for (int half = 0; half < 2; half++) {
            uint32_t ph[2][4], pl[2][4];
#pragma unroll
            for (int k2 = 0; k2 < 2; k2++) {
                const int kt16 = half * 2 + k2;
                split_hilo(sc[2 * kt16][0],     sc[2 * kt16][1],     ph[k2][0], pl[k2][0]);
                split_hilo(sc[2 * kt16][2],     sc[2 * kt16][3],     ph[k2][1], pl[k2][1]);
                split_hilo(sc[2 * kt16 + 1][0], sc[2 * kt16 + 1][1], ph[k2][2], pl[k2][2]);
                split_hilo(sc[2 * kt16 + 1][2], sc[2 * kt16 + 1][3], ph[k2][3], pl[k2][3]);
            }
            uint32_t vh4[2][4], vl4[2][4];
            {
                const uint32_t a0 = st + 2 * A_ARR + (uint32_t)(half * 2 * 16) * 144 + vlane;
                ldmx4t(vh4[0], a0);
                ldmx4t(vl4[0], a0 + A_ARR);
            }
#pragma unroll
            for (int step = 0; step < 8; step++) {
                const int buf = step & 1;
                if (step < 7) {
                    const int sn = step + 1;
                    const uint32_t an = st + 2 * A_ARR
                        + (uint32_t)((half * 2 + (sn >> 2)) * 16) * 144 + (sn & 3) * 32 + vlane;
                    ldmx4t(vh4[buf ^ 1], an);
                    ldmx4t(vl4[buf ^ 1], an + A_ARR);
                }
                const int k2 = step >> 2, db = step & 3;
                float* c0 = acc[2 * db];
                float* c1 = acc[2 * db + 1];
                mma16816(c0, ph[k2], vh4[buf][0], vh4[buf][1]);
                mma16816(c0, pl[k2], vh4[buf][0], vh4[buf][1]);
                mma16816(c0, ph[k2], vl4[buf][0], vl4[buf][1]);
                mma16816(c1, ph[k2], vh4[buf][2], vh4[buf][3]);
                mma16816(c1, pl[k2], vh4[buf][2], vh4[buf][3]);
                mma16816(c1, ph[k2], vl4[buf][2], vl4[buf][3]);
            }
        }
    }

    // ---- normalize + write ctx as bf16 hi/lo ----
    const float i0 = 1.0f / lsum0, i1 = 1.0f / lsum1;
    const int srow = q0 + w * 16 + (l >> 2);
    const int colb = h * 64 + 2 * (l & 3);
#pragma unroll
    for (int nt = 0; nt < 8; nt++) {
        const int col = colb + nt * 8;
        uint32_t hiw, low;
        split_hilo(acc[nt][0] * i0, acc[nt][1] * i0, hiw, low);
        const size_t off0 = ((size_t)srow * 4 + b) * HID + col;
        *(uint32_t*)(ctxh + off0) = hiw;
        *(uint32_t*)(ctxl + off0) = low;
        split_hilo(acc[nt][2] * i1, acc[nt][3] * i1, hiw, low);
        const size_t off1 = ((size_t)(srow + 8) * 4 + b) * HID + col;
        *(uint32_t*)(ctxh + off1) = hiw;
        *(uint32_t*)(ctxl + off1) = low;
    }
}

// ---------------------------------------------------------------------------
// Launch
// ---------------------------------------------------------------------------
extern "C" void kernel_launch(void* const* d_in, const int* in_sizes, int n_in,
                              void* d_out, int out_size) {
    const float* hs      = (const float*)d_in[0];
    const void*  mask    = d_in[1];
    const float* W_qkv   = (const float*)d_in[2];
    const float* b_qkv   = (const float*)d_in[3];
    const float* W_dense = (const float*)d_in[4];
    const float* b_dense = (const float*)d_in[5];
    float* out = (float*)d_out;

    __nv_bfloat16 *pAh, *pAl, *pWqh, *pWql, *pWdh, *pWdl;
    __nv_bfloat16 *Qh, *Ql, *Kh, *Kl, *Vh, *Vl;
    uint32_t* maskbits;
    cudaGetSymbolAddress((void**)&pAh, g_pA_hi);
    cudaGetSymbolAddress((void**)&pAl, g_pA_lo);
    cudaGetSymbolAddress((void**)&pWqh, g_pWq_hi);
    cudaGetSymbolAddress((void**)&pWql, g_pWq_lo);
    cudaGetSymbolAddress((void**)&pWdh, g_pWd_hi);
    cudaGetSymbolAddress((void**)&pWdl, g_pWd_lo);
    cudaGetSymbolAddress((void**)&Qh, g_Qh);
    cudaGetSymbolAddress((void**)&Ql, g_Ql);
    cudaGetSymbolAddress((void**)&Kh, g_Kh);
    cudaGetSymbolAddress((void**)&Kl, g_Kl);
    cudaGetSymbolAddress((void**)&Vh, g_Vh);
    cudaGetSymbolAddress((void**)&Vl, g_Vl);
    cudaGetSymbolAddress((void**)&maskbits, g_mask_bits);

    cudaFuncSetAttribute(gemm_mma, cudaFuncAttributeMaxDynamicSharedMemorySize, GT_SMEM);
    cudaFuncSetAttribute(attention_mma, cudaFuncAttributeMaxDynamicSharedMemorySize, A_SMEM);

    // 0) mask dtype + fragment-layout bit conversion
    detect_mask_dtype<<<1, 32>>>((const int*)mask);
    convert_mask_frag<<<BATCH * 16 * 32, 256>>>(mask, maskbits);

    // 1) fused pack: hs + W_qkv + W_dense (one launch)
    pack_all<<<PK_ALL / 256, 256>>>(hs, W_qkv, W_dense,
                                    pAh, pAl, pWqh, pWql, pWdh, pWdl);

    // 2) QKV GEMM -> split bf16 hi/lo Q/K/V (Q pre-scaled to log2 domain)
    gemm_mma<<<dim3(QKV_N / 128, M_ROWS / 128), 256, GT_SMEM>>>(
        pAh, pAl, pWqh, pWql, b_qkv, nullptr, QKV_N, 1, Qh, Ql, Kh, Kl, Vh, Vl);

    // 3) tensor-core flash attention -> ctx hi/lo (into pA buffers)
    attention_mma<<<dim3(S_LEN / 128, BATCH * NHEADS), 256, A_SMEM>>>(
        maskbits, Qh, Ql, Kh, Kl, Vh, Vl, pAh, pAl);

    // 4) dense GEMM -> out
    gemm_mma<<<dim3(HID / 128, M_ROWS / 128), 256, GT_SMEM>>>(
        pAh, pAl, pWdh, pWdl, b_dense, out, HID, 0,
        nullptr, nullptr, nullptr, nullptr, nullptr, nullptr);
}